// round 13
// baseline (speedup 1.0000x reference)
#include <cuda_runtime.h>
#include <cuda_bf16.h>
#include <cstdint>
#include <math.h>

// Problem constants
#define Bb   16
#define Tt   16
#define Ll   512
#define Hdim 768
#define ML   (Bb * Ll)            // 8192 rows of hn

#define SELU_SCALE 1.0507009873554805f
#define SELU_SA    1.7580993408473766f   // scale * alpha

// Scratch (device globals; no runtime allocation)
__device__ float g_WET[(size_t)Hdim * ML];              // WE^T: [H, B*L]
__device__ float g_WDp[4][(size_t)Bb * Tt * Hdim];      // WD K-split partials
__device__ __nv_bfloat16 g_Ah[(size_t)ML * Hdim];       // hn hi
__device__ __nv_bfloat16 g_Al[(size_t)ML * Hdim];       // hn lo
__device__ __nv_bfloat16 g_Bh[(size_t)Hdim * Hdim];     // W1 hi
__device__ __nv_bfloat16 g_Bl[(size_t)Hdim * Hdim];     // W1 lo

__device__ __forceinline__ int idx_stride(const int* __restrict__ xp) {
    return (xp[1] == 0) ? 2 : 1;   // int64 vs int32 index dtype
}

__device__ __forceinline__ uint32_t smem_u32(const void* p) {
    uint32_t a;
    asm("{ .reg .u64 t; cvta.to.shared.u64 t, %1; cvt.u32.u64 %0, t; }"
        : "=r"(a) : "l"(p));
    return a;
}
__device__ __forceinline__ void cp_async16(uint32_t sa, const void* ga) {
    asm volatile("cp.async.cg.shared.global [%0], [%1], 16;"
                 :: "r"(sa), "l"(ga) : "memory");
}
__device__ __forceinline__ void cp_commit() {
    asm volatile("cp.async.commit_group;" ::: "memory");
}
__device__ __forceinline__ void cp_wait0() {
    asm volatile("cp.async.wait_group 0;" ::: "memory");
}
__device__ __forceinline__ void cp_wait1() {
    asm volatile("cp.async.wait_group 1;" ::: "memory");
}
__device__ __forceinline__ void ldsm_x4(uint32_t* r, uint32_t addr) {
    asm volatile("ldmatrix.sync.aligned.m8n8.x4.shared.b16 {%0,%1,%2,%3}, [%4];"
                 : "=r"(r[0]), "=r"(r[1]), "=r"(r[2]), "=r"(r[3]) : "r"(addr));
}
__device__ __forceinline__ void mma_bf16(float* c, const uint32_t* a, const uint32_t* b) {
    asm volatile(
        "mma.sync.aligned.m16n8k16.row.col.f32.bf16.bf16.f32 "
        "{%0,%1,%2,%3}, {%4,%5,%6,%7}, {%8,%9}, {%0,%1,%2,%3};"
        : "+f"(c[0]), "+f"(c[1]), "+f"(c[2]), "+f"(c[3])
        : "r"(a[0]), "r"(a[1]), "r"(a[2]), "r"(a[3]), "r"(b[0]), "r"(b[1]));
}

// ---------------------------------------------------------------------------
// fp32 -> (bf16 hi, bf16 lo) split, vectorized by float4
// ---------------------------------------------------------------------------
__global__ __launch_bounds__(256) void split_kernel(
    const float* __restrict__ src, __nv_bfloat16* __restrict__ hi,
    __nv_bfloat16* __restrict__ lo, int n4)
{
    int i = blockIdx.x * 256 + threadIdx.x;
    if (i >= n4) return;
    float4 v = ((const float4*)src)[i];
    float f[4] = {v.x, v.y, v.z, v.w};
    __nv_bfloat16 h[4], l[4];
#pragma unroll
    for (int j = 0; j < 4; j++) {
        h[j] = __float2bfloat16(f[j]);
        l[j] = __float2bfloat16(f[j] - __bfloat162float(h[j]));
    }
    __nv_bfloat162 h0; h0.x = h[0]; h0.y = h[1];
    __nv_bfloat162 h1; h1.x = h[2]; h1.y = h[3];
    __nv_bfloat162 l0; l0.x = l[0]; l0.y = l[1];
    __nv_bfloat162 l1; l1.x = l[2]; l1.y = l[3];
    ((__nv_bfloat162*)hi)[2 * i]     = h0;
    ((__nv_bfloat162*)hi)[2 * i + 1] = h1;
    ((__nv_bfloat162*)lo)[2 * i]     = l0;
    ((__nv_bfloat162*)lo)[2 * i + 1] = l1;
}

// ---------------------------------------------------------------------------
// Kernel A: WE^T = (hn @ W1^T)^T via mma.sync bf16 split (AhBh + AhBl + AlBh).
// CTA tile 256(m) x 128(n), BK=32, 16 warps each 64x32, cp.async 3-stage.
// smem stage (row stride 80B, ldmatrix conflict-free):
//   Ah @ 0 (256x80), Al @ 20480, Bh @ 40960 (128x80), Bl @ 51200
//   stage = 61440, 3 stages = 184320.
// Pipeline: wait_group(1) keeps one chunk's loads in flight under compute.
// Epilogue: two 128-row rounds through smem, transposed coalesced stores.
// ---------------------------------------------------------------------------
#define ROWB      80
#define ATILEB    (256 * ROWB)       // 20480
#define BTILEB    (128 * ROWB)       // 10240
#define STAGEB    (2 * ATILEB + 2 * BTILEB)   // 61440
#define WE_SMEM   (3 * STAGEB)       // 184320 >= 128*132*4 epilogue round

__global__ __launch_bounds__(512) void we_mma_kernel()
{
    extern __shared__ char smem[];
    const uint32_t sb = smem_u32(smem);

    const int tid    = threadIdx.x;
    const int lane   = tid & 31;
    const int wid    = tid >> 5;
    const int m0     = blockIdx.y * 256;
    const int n0     = blockIdx.x * 128;
    const int warp_m = (wid & 3) * 64;
    const int warp_n = (wid >> 2) * 32;

    // ldmatrix per-lane row/seg constants
    const int a_row = lane & 15;            // row within 16
    const int a_ks  = lane >> 4;            // 16B seg within k16
    const int b_row = lane & 7;
    const int b_nt  = (lane >> 4);          // n-subtile within pair
    const int b_ks  = (lane >> 3) & 1;      // 16B seg

    float acc[4][4][4];
#pragma unroll
    for (int i = 0; i < 4; i++)
#pragma unroll
        for (int j = 0; j < 4; j++)
#pragma unroll
            for (int q = 0; q < 4; q++) acc[i][j][q] = 0.f;

    // cp.async mapping: A tiles 1024 segs (rows tid>>2, +128), B tiles 512 segs
    const int rA = tid >> 2;                // 0..127
    const int g  = (tid & 3);               // 16B seg within 64-col chunk

    const __nv_bfloat16* pAh = g_Ah + (size_t)m0 * Hdim;
    const __nv_bfloat16* pAl = g_Al + (size_t)m0 * Hdim;
    const __nv_bfloat16* pBh = g_Bh + (size_t)n0 * Hdim;
    const __nv_bfloat16* pBl = g_Bl + (size_t)n0 * Hdim;

    auto issue_stage = [&](int s, int c) {
        const uint32_t stb = sb + s * STAGEB;
        const int koff = c * 32;
        // Ah / Al: rows rA and rA+128
        cp_async16(stb + rA * ROWB + g * 16,
                   pAh + (size_t)rA * Hdim + koff + g * 8);
        cp_async16(stb + (rA + 128) * ROWB + g * 16,
                   pAh + (size_t)(rA + 128) * Hdim + koff + g * 8);
        cp_async16(stb + ATILEB + rA * ROWB + g * 16,
                   pAl + (size_t)rA * Hdim + koff + g * 8);
        cp_async16(stb + ATILEB + (rA + 128) * ROWB + g * 16,
                   pAl + (size_t)(rA + 128) * Hdim + koff + g * 8);
        // Bh / Bl: rows rA (0..127)
        cp_async16(stb + 2 * ATILEB + rA * ROWB + g * 16,
                   pBh + (size_t)rA * Hdim + koff + g * 8);
        cp_async16(stb + 2 * ATILEB + BTILEB + rA * ROWB + g * 16,
                   pBl + (size_t)rA * Hdim + koff + g * 8);
        cp_commit();
    };

    issue_stage(0, 0);
    issue_stage(1, 1);

    for (int c = 0; c < 24; c++) {
        const int s = c % 3;
        // chunk c must be complete; c+1 may remain in flight (except at tail)
        if (c < 23) cp_wait1(); else cp_wait0();
        __syncthreads();
        if (c + 2 < 24) issue_stage((c + 2) % 3, c + 2);

        const uint32_t stb = sb + s * STAGEB;
#pragma unroll
        for (int ks = 0; ks < 2; ks++) {
            uint32_t af[4][4], bh[4][2], bl[4][2];
            // A-hi fragments (4 m-tiles of this warp's 64 rows)
#pragma unroll
            for (int mt = 0; mt < 4; mt++)
                ldsm_x4(af[mt], stb +
                        (warp_m + mt * 16 + a_row) * ROWB + ks * 32 + a_ks * 16);
            // B fragments
#pragma unroll
            for (int q = 0; q < 2; q++) {
                uint32_t t4[4];
                ldsm_x4(t4, stb + 2 * ATILEB +
                        (warp_n + q * 16 + b_nt * 8 + b_row) * ROWB + ks * 32 + b_ks * 16);
                bh[2 * q][0] = t4[0]; bh[2 * q][1] = t4[1];
                bh[2 * q + 1][0] = t4[2]; bh[2 * q + 1][1] = t4[3];
                ldsm_x4(t4, stb + 2 * ATILEB + BTILEB +
                        (warp_n + q * 16 + b_nt * 8 + b_row) * ROWB + ks * 32 + b_ks * 16);
                bl[2 * q][0] = t4[0]; bl[2 * q][1] = t4[1];
                bl[2 * q + 1][0] = t4[2]; bl[2 * q + 1][1] = t4[3];
            }
            // Ah*Bh + Ah*Bl
#pragma unroll
            for (int mt = 0; mt < 4; mt++)
#pragma unroll
                for (int nt = 0; nt < 4; nt++) {
                    mma_bf16(acc[mt][nt], af[mt], bh[nt]);
                    mma_bf16(acc[mt][nt], af[mt], bl[nt]);
                }
            // Al*Bh (reuse af regs)
#pragma unroll
            for (int mt = 0; mt < 4; mt++)
                ldsm_x4(af[mt], stb + ATILEB +
                        (warp_m + mt * 16 + a_row) * ROWB + ks * 32 + a_ks * 16);
#pragma unroll
            for (int mt = 0; mt < 4; mt++)
#pragma unroll
                for (int nt = 0; nt < 4; nt++)
                    mma_bf16(acc[mt][nt], af[mt], bh[nt]);
        }
    }
    __syncthreads();

    // Epilogue: two rounds of 128 m-rows through smem (stride 132)
    float (*smT)[132] = (float (*)[132])smem;
    const int rq = lane >> 2;          // row within 8
    const int cq = 2 * (lane & 3);     // col pair
#pragma unroll
    for (int r = 0; r < 2; r++) {
        if ((warp_m >> 7) == r) {
            const int mb = warp_m - r * 128;
#pragma unroll
            for (int mt = 0; mt < 4; mt++)
#pragma unroll
                for (int nt = 0; nt < 4; nt++) {
                    const int mm = mb + mt * 16 + rq;
                    const int nn = warp_n + nt * 8 + cq;
                    smT[mm][nn]         = acc[mt][nt][0];
                    smT[mm][nn + 1]     = acc[mt][nt][1];
                    smT[mm + 8][nn]     = acc[mt][nt][2];
                    smT[mm + 8][nn + 1] = acc[mt][nt][3];
                }
        }
        __syncthreads();
        // WE^T[h=n0+hh][m0 + r*128 + mm]: warp handles 8 h-rows this round
#pragma unroll
        for (int rr = 0; rr < 8; rr++) {
            const int hh = wid * 8 + rr;
            float4 v;
            v.x = smT[lane * 4 + 0][hh];
            v.y = smT[lane * 4 + 1][hh];
            v.z = smT[lane * 4 + 2][hh];
            v.w = smT[lane * 4 + 3][hh];
            *(float4*)(g_WET + (size_t)(n0 + hh) * ML + m0 + r * 128 + lane * 4) = v;
        }
        __syncthreads();
    }
}

// ---------------------------------------------------------------------------
// Kernel B: WD partials. grid (12, 4, 4); z-block covers K in [z*192, z*192+192).
// 64x64 tile, 256 threads, 4x4 microtile. Partials summed in score_loss.
// ---------------------------------------------------------------------------
__global__ __launch_bounds__(256) void wd_gemm_kernel(
    const float* __restrict__ D, const float* __restrict__ W2,
    const int* __restrict__ xp, const int* __restrict__ yp)
{
    __shared__ float As[16][68];
    __shared__ float Bs[16][68];

    const int st  = idx_stride(xp);
    const int tid = threadIdx.x;
    const int m0  = blockIdx.y * 64;
    const int n0  = blockIdx.x * 64;
    const int z   = blockIdx.z;
    const int tm  = (tid >> 4) * 4;
    const int tn  = (tid & 15) * 4;

    const int row = tid >> 2;
    const int kg  = (tid & 3) * 4;
    const int r   = m0 + row;
    const int bi  = r >> 4;
    const int Yv  = yp[r * st];
    const float* arow = D + ((size_t)bi * Ll + (size_t)Yv) * Hdim;
    const float* brow = W2 + (size_t)(n0 + row) * Hdim;

    float acc[4][4];
#pragma unroll
    for (int i = 0; i < 4; i++)
#pragma unroll
        for (int j = 0; j < 4; j++) acc[i][j] = 0.f;

    const int kbeg = z * 192, kend = kbeg + 192;
    for (int k0 = kbeg; k0 < kend; k0 += 16) {
        float4 va = *(const float4*)(arow + k0 + kg);
        As[kg + 0][row] = va.x; As[kg + 1][row] = va.y;
        As[kg + 2][row] = va.z; As[kg + 3][row] = va.w;
        float4 vb = *(const float4*)(brow + k0 + kg);
        Bs[kg + 0][row] = vb.x; Bs[kg + 1][row] = vb.y;
        Bs[kg + 2][row] = vb.z; Bs[kg + 3][row] = vb.w;
        __syncthreads();

#pragma unroll
        for (int kk = 0; kk < 16; kk++) {
            float a[4], b[4];
            *(float4*)&a[0] = *(const float4*)&As[kk][tm];
            *(float4*)&b[0] = *(const float4*)&Bs[kk][tn];
#pragma unroll
            for (int i = 0; i < 4; i++)
#pragma unroll
                for (int j = 0; j < 4; j++)
                    acc[i][j] = fmaf(a[i], b[j], acc[i][j]);
        }
        __syncthreads();
    }

#pragma unroll
    for (int i = 0; i < 4; i++) {
        float4 o;
        o.x = acc[i][0]; o.y = acc[i][1]; o.z = acc[i][2]; o.w = acc[i][3];
        *(float4*)(&g_WDp[z][(size_t)(m0 + tm + i) * Hdim + n0 + tn]) = o;
    }
}

// ---------------------------------------------------------------------------
// Kernel C: fused scores + masked log-softmax + NLL. One block per (b,t),
// 512 threads, thread per l reading WE^T columns (coalesced).
// ---------------------------------------------------------------------------
__device__ __forceinline__ float selu1(float x) {
    float e = __expf(x);
    return (x > 0.f) ? SELU_SCALE * x : fmaf(SELU_SA, e, -SELU_SA);
}

__global__ __launch_bounds__(512) void score_loss_kernel(
    const float* __restrict__ V,
    const int* __restrict__ xp, const int* __restrict__ yp,
    float* __restrict__ out)
{
    __shared__ float wd_s[Hdim];
    __shared__ float v_s[Hdim];
    __shared__ float red[16];
    __shared__ float bcast;
    __shared__ float gold_s;

    const int bt   = blockIdx.x;
    const int b    = bt >> 4;
    const int tid  = threadIdx.x;
    const int lane = tid & 31;
    const int warp = tid >> 5;

    const int st = idx_stride(xp);
    const int X  = xp[bt * st];
    const int Y  = yp[bt * st];

    for (int i = tid; i < Hdim; i += 512) {
        const size_t o = (size_t)bt * Hdim + i;
        wd_s[i] = (g_WDp[0][o] + g_WDp[1][o]) + (g_WDp[2][o] + g_WDp[3][o]);
        v_s[i]  = V[i];
    }
    __syncthreads();

    const int  l      = X + tid;
    const bool active = (l < Ll);

    float sc = -3.4e38f;
    if (active) {
        const float* col = g_WET + (size_t)b * Ll + l;   // + h*ML per row
        float s0 = 0.f, s1 = 0.f, s2 = 0.f, s3 = 0.f;
#pragma unroll 4
        for (int h = 0; h < Hdim; h += 4) {
            float w0 = col[(size_t)(h + 0) * ML];
            float w1 = col[(size_t)(h + 1) * ML];
            float w2 = col[(size_t)(h + 2) * ML];
            float w3 = col[(size_t)(h + 3) * ML];
            s0 = fmaf(selu1(w0 + wd_s[h + 0]), v_s[h + 0], s0);
            s1 = fmaf(selu1(w1 + wd_s[h + 1]), v_s[h + 1], s1);
            s2 = fmaf(selu1(w2 + wd_s[h + 2]), v_s[h + 2], s2);
            s3 = fmaf(selu1(w3 + wd_s[h + 3]), v_s[h + 3], s3);
        }
        sc = selu1((s0 + s1) + (s2 + s3));
        if (l == Y) gold_s = sc;
    }

    // block max
    float m = sc;
#pragma unroll
    for (int o = 16; o > 0; o >>= 1)
        m = fmaxf(m, __shfl_xor_sync(0xffffffffu, m, o));
    if (lane == 0) red[warp] = m;
    __syncthreads();
    if (tid == 0) {
        float mm = red[0];
#pragma unroll
        for (int i = 1; i < 16; i++) mm = fmaxf(mm, red[i]);
        bcast = mm;
    }
    __syncthreads();
    const float mx = bcast;

    // block sum of exp
    float e = active ? __expf(sc - mx) : 0.f;
#pragma unroll
    for (int o = 16; o > 0; o >>= 1)
        e += __shfl_xor_sync(0xffffffffu, e, o);
    if (lane == 0) red[warp] = e;
    __syncthreads();

    if (tid == 0) {
        float tot = 0.f;
#pragma unroll
        for (int i = 0; i < 16; i++) tot += red[i];
        float lse = mx + __logf(tot);
        atomicAdd(out, (lse - gold_s) * (1.0f / (Bb * Tt)));
    }
}

__global__ void init_out_kernel(float* out) { out[0] = 0.f; }

// ---------------------------------------------------------------------------
extern "C" void kernel_launch(void* const* d_in, const int* in_sizes, int n_in,
                              void* d_out, int out_size) {
    const float* hn  = (const float*)d_in[0];
    const float* dec = (const float*)d_in[1];
    const float* W1  = (const float*)d_in[2];
    const float* W2  = (const float*)d_in[3];
    const float* V   = (const float*)d_in[4];
    const int*   Xi  = (const int*)d_in[5];
    const int*   Yi  = (const int*)d_in[6];
    float* out = (float*)d_out;

    cudaFuncSetAttribute(we_mma_kernel,
                         cudaFuncAttributeMaxDynamicSharedMemorySize, WE_SMEM);

    __nv_bfloat16 *ah, *al, *bh, *bl;
    cudaGetSymbolAddress((void**)&ah, g_Ah);
    cudaGetSymbolAddress((void**)&al, g_Al);
    cudaGetSymbolAddress((void**)&bh, g_Bh);
    cudaGetSymbolAddress((void**)&bl, g_Bl);

    init_out_kernel<<<1, 1>>>(out);

    const int nA4 = (ML * Hdim) / 4;
    const int nW4 = (Hdim * Hdim) / 4;
    split_kernel<<<(nA4 + 255) / 256, 256>>>(hn, ah, al, nA4);
    split_kernel<<<(nW4 + 255) / 256, 256>>>(W1, bh, bl, nW4);

    we_mma_kernel<<<dim3(Hdim / 128, ML / 256), 512, WE_SMEM>>>();
    wd_gemm_kernel<<<dim3(Hdim / 64, (Bb * Tt) / 64, 4), 256>>>(dec, W2, Xi, Yi);
    score_loss_kernel<<<Bb * Tt, 512>>>(V, Xi, Yi, out);
}

// round 16
// speedup vs baseline: 1.1486x; 1.1486x over previous
#include <cuda_runtime.h>
#include <cuda_bf16.h>
#include <cstdint>
#include <math.h>

// Problem constants
#define Bb   16
#define Tt   16
#define Ll   512
#define Hdim 768
#define ML   (Bb * Ll)            // 8192 rows of hn

#define SELU_SCALE 1.0507009873554805f
#define SELU_SA    1.7580993408473766f   // scale * alpha

// Scratch (device globals; no runtime allocation)
__device__ float g_WET[(size_t)Hdim * ML];              // WE^T: [H, B*L]
__device__ float g_WDp[4][(size_t)Bb * Tt * Hdim];      // WD K-split partials
__device__ __nv_bfloat16 g_Ah[(size_t)ML * Hdim];       // hn hi
__device__ __nv_bfloat16 g_Al[(size_t)ML * Hdim];       // hn lo
__device__ __nv_bfloat16 g_Bh[(size_t)Hdim * Hdim];     // W1 hi
__device__ __nv_bfloat16 g_Bl[(size_t)Hdim * Hdim];     // W1 lo

__device__ __forceinline__ int idx_stride(const int* __restrict__ xp) {
    return (xp[1] == 0) ? 2 : 1;   // int64 vs int32 index dtype
}

__device__ __forceinline__ uint32_t smem_u32(const void* p) {
    uint32_t a;
    asm("{ .reg .u64 t; cvta.to.shared.u64 t, %1; cvt.u32.u64 %0, t; }"
        : "=r"(a) : "l"(p));
    return a;
}
__device__ __forceinline__ void cp_async16(uint32_t sa, const void* ga) {
    asm volatile("cp.async.cg.shared.global [%0], [%1], 16;"
                 :: "r"(sa), "l"(ga) : "memory");
}
__device__ __forceinline__ void cp_commit() {
    asm volatile("cp.async.commit_group;" ::: "memory");
}
__device__ __forceinline__ void cp_wait0() {
    asm volatile("cp.async.wait_group 0;" ::: "memory");
}
__device__ __forceinline__ void ldsm_x4(uint32_t* r, uint32_t addr) {
    asm volatile("ldmatrix.sync.aligned.m8n8.x4.shared.b16 {%0,%1,%2,%3}, [%4];"
                 : "=r"(r[0]), "=r"(r[1]), "=r"(r[2]), "=r"(r[3]) : "r"(addr));
}
__device__ __forceinline__ void mma_bf16(float* c, const uint32_t* a, const uint32_t* b) {
    asm volatile(
        "mma.sync.aligned.m16n8k16.row.col.f32.bf16.bf16.f32 "
        "{%0,%1,%2,%3}, {%4,%5,%6,%7}, {%8,%9}, {%0,%1,%2,%3};"
        : "+f"(c[0]), "+f"(c[1]), "+f"(c[2]), "+f"(c[3])
        : "r"(a[0]), "r"(a[1]), "r"(a[2]), "r"(a[3]), "r"(b[0]), "r"(b[1]));
}

// ---------------------------------------------------------------------------
// fp32 -> (bf16 hi, bf16 lo) split, vectorized by float4
// ---------------------------------------------------------------------------
__global__ __launch_bounds__(256) void split_kernel(
    const float* __restrict__ src, __nv_bfloat16* __restrict__ hi,
    __nv_bfloat16* __restrict__ lo, int n4)
{
    int i = blockIdx.x * 256 + threadIdx.x;
    if (i >= n4) return;
    float4 v = ((const float4*)src)[i];
    float f[4] = {v.x, v.y, v.z, v.w};
    __nv_bfloat16 h[4], l[4];
#pragma unroll
    for (int j = 0; j < 4; j++) {
        h[j] = __float2bfloat16(f[j]);
        l[j] = __float2bfloat16(f[j] - __bfloat162float(h[j]));
    }
    __nv_bfloat162 h0; h0.x = h[0]; h0.y = h[1];
    __nv_bfloat162 h1; h1.x = h[2]; h1.y = h[3];
    __nv_bfloat162 l0; l0.x = l[0]; l0.y = l[1];
    __nv_bfloat162 l1; l1.x = l[2]; l1.y = l[3];
    ((__nv_bfloat162*)hi)[2 * i]     = h0;
    ((__nv_bfloat162*)hi)[2 * i + 1] = h1;
    ((__nv_bfloat162*)lo)[2 * i]     = l0;
    ((__nv_bfloat162*)lo)[2 * i + 1] = l1;
}

// ---------------------------------------------------------------------------
// Kernel A: WE^T = (hn @ W1^T)^T via mma.sync bf16 split (AhBh + AhBl + AlBh).
// ROUND-7 CONFIG (measured 101us): CTA tile 128x128, BK=32, 8 warps each
// 64x32, cp.async 2-stage, 82KB smem -> 2 CTAs/SM co-residency.
// smem stage layout (row stride 80B, ldmatrix conflict-free):
//   Ah @ 0, Al @ 10240, Bh @ 20480, Bl @ 30720 ; stage 40960, 2 stages.
// Epilogue: stage D (128x128 f32) in smem, write transposed coalesced.
// ---------------------------------------------------------------------------
#define ROWB      80
#define TILEB     (128 * ROWB)       // 10240
#define STAGEB    (4 * TILEB)        // 40960
#define WE_SMEM   (2 * STAGEB)       // 81920 >= 128*132*4 epilogue

__global__ __launch_bounds__(256) void we_mma_kernel()
{
    extern __shared__ char smem[];
    const uint32_t sb = smem_u32(smem);

    const int tid    = threadIdx.x;
    const int lane   = tid & 31;
    const int wid    = tid >> 5;
    const int m0     = blockIdx.y * 128;
    const int n0     = blockIdx.x * 128;
    const int warp_m = (wid & 1) * 64;
    const int warp_n = (wid >> 1) * 32;

    // ldmatrix per-lane row/seg constants
    const int a_row = lane & 15;            // row within 16
    const int a_ks  = lane >> 4;            // 16B seg within k16
    const int b_row = lane & 7;
    const int b_nt  = (lane >> 4);          // 0..1 (n-subtile within pair)
    const int b_ks  = (lane >> 3) & 1;      // 16B seg

    float acc[4][4][4];
#pragma unroll
    for (int i = 0; i < 4; i++)
#pragma unroll
        for (int j = 0; j < 4; j++)
#pragma unroll
            for (int q = 0; q < 4; q++) acc[i][j][q] = 0.f;

    // cp.async per-thread segments: per tile 512 segs (128 rows x 4 x 16B)
    const int r0 = tid >> 2, r1 = (tid + 256) >> 2;
    const int g0 = (tid & 3), g1 = (tid & 3);

    const __nv_bfloat16* srcs[4] = {
        g_Ah + (size_t)m0 * Hdim, g_Al + (size_t)m0 * Hdim,
        g_Bh + (size_t)n0 * Hdim, g_Bl + (size_t)n0 * Hdim };

    auto issue_stage = [&](int s, int c) {
        const uint32_t stb = sb + s * STAGEB;
#pragma unroll
        for (int t = 0; t < 4; t++) {
            const __nv_bfloat16* g = srcs[t] + c * 32;
            cp_async16(stb + t * TILEB + r0 * ROWB + g0 * 16,
                       g + (size_t)r0 * Hdim + g0 * 8);
            cp_async16(stb + t * TILEB + r1 * ROWB + g1 * 16,
                       g + (size_t)r1 * Hdim + g1 * 8);
        }
        cp_commit();
    };

    issue_stage(0, 0);

    for (int c = 0; c < 24; c++) {
        const int s = c & 1;
        cp_wait0();
        __syncthreads();
        if (c + 1 < 24) issue_stage(s ^ 1, c + 1);

        const uint32_t stb = sb + s * STAGEB;
#pragma unroll
        for (int ks = 0; ks < 2; ks++) {
            uint32_t af[4][4], bh[4][2], bl[4][2];
            // A-hi fragments (4 m-tiles)
#pragma unroll
            for (int mt = 0; mt < 4; mt++)
                ldsm_x4(af[mt], stb + 0 * TILEB +
                        (warp_m + mt * 16 + a_row) * ROWB + ks * 32 + a_ks * 16);
            // B fragments: 2 x4 per matrix, each covers 2 n-subtiles
#pragma unroll
            for (int q = 0; q < 2; q++) {
                uint32_t t4[4];
                ldsm_x4(t4, stb + 2 * TILEB +
                        (warp_n + q * 16 + b_nt * 8 + b_row) * ROWB + ks * 32 + b_ks * 16);
                bh[2 * q][0] = t4[0]; bh[2 * q][1] = t4[1];
                bh[2 * q + 1][0] = t4[2]; bh[2 * q + 1][1] = t4[3];
                ldsm_x4(t4, stb + 3 * TILEB +
                        (warp_n + q * 16 + b_nt * 8 + b_row) * ROWB + ks * 32 + b_ks * 16);
                bl[2 * q][0] = t4[0]; bl[2 * q][1] = t4[1];
                bl[2 * q + 1][0] = t4[2]; bl[2 * q + 1][1] = t4[3];
            }
            // Ah*Bh + Ah*Bl
#pragma unroll
            for (int mt = 0; mt < 4; mt++)
#pragma unroll
                for (int nt = 0; nt < 4; nt++) {
                    mma_bf16(acc[mt][nt], af[mt], bh[nt]);
                    mma_bf16(acc[mt][nt], af[mt], bl[nt]);
                }
            // Al*Bh (reuse af regs)
#pragma unroll
            for (int mt = 0; mt < 4; mt++)
                ldsm_x4(af[mt], stb + 1 * TILEB +
                        (warp_m + mt * 16 + a_row) * ROWB + ks * 32 + a_ks * 16);
#pragma unroll
            for (int mt = 0; mt < 4; mt++)
#pragma unroll
                for (int nt = 0; nt < 4; nt++)
                    mma_bf16(acc[mt][nt], af[mt], bh[nt]);
        }
    }
    __syncthreads();

    // Epilogue: D -> smem [m][n] (stride 132), then transposed coalesced store
    float (*smT)[132] = (float (*)[132])smem;
    {
        const int rq = lane >> 2;          // row within 8
        const int cq = 2 * (lane & 3);     // col pair
#pragma unroll
        for (int mt = 0; mt < 4; mt++)
#pragma unroll
            for (int nt = 0; nt < 4; nt++) {
                const int mm = warp_m + mt * 16 + rq;
                const int nn = warp_n + nt * 8 + cq;
                smT[mm][nn]         = acc[mt][nt][0];
                smT[mm][nn + 1]     = acc[mt][nt][1];
                smT[mm + 8][nn]     = acc[mt][nt][2];
                smT[mm + 8][nn + 1] = acc[mt][nt][3];
            }
    }
    __syncthreads();

    // WE^T[h = n0+hh][m0 + mm]: warp handles 16 h-rows, lane writes float4 of m
#pragma unroll
    for (int rr = 0; rr < 16; rr++) {
        const int hh = wid * 16 + rr;
        float4 v;
        v.x = smT[lane * 4 + 0][hh];
        v.y = smT[lane * 4 + 1][hh];
        v.z = smT[lane * 4 + 2][hh];
        v.w = smT[lane * 4 + 3][hh];
        *(float4*)(g_WET + (size_t)(n0 + hh) * ML + m0 + lane * 4) = v;
    }
}

// ---------------------------------------------------------------------------
// Kernel B: WD partials. grid (12, 4, 4); z-block covers K in [z*192, z*192+192).
// 64x64 tile, 256 threads, 4x4 microtile. Partials summed in score_loss.
// ---------------------------------------------------------------------------
__global__ __launch_bounds__(256) void wd_gemm_kernel(
    const float* __restrict__ D, const float* __restrict__ W2,
    const int* __restrict__ xp, const int* __restrict__ yp)
{
    __shared__ float As[16][68];
    __shared__ float Bs[16][68];

    const int st  = idx_stride(xp);
    const int tid = threadIdx.x;
    const int m0  = blockIdx.y * 64;
    const int n0  = blockIdx.x * 64;
    const int z   = blockIdx.z;
    const int tm  = (tid >> 4) * 4;
    const int tn  = (tid & 15) * 4;

    const int row = tid >> 2;
    const int kg  = (tid & 3) * 4;
    const int r   = m0 + row;
    const int bi  = r >> 4;
    const int Yv  = yp[r * st];
    const float* arow = D + ((size_t)bi * Ll + (size_t)Yv) * Hdim;
    const float* brow = W2 + (size_t)(n0 + row) * Hdim;

    float acc[4][4];
#pragma unroll
    for (int i = 0; i < 4; i++)
#pragma unroll
        for (int j = 0; j < 4; j++) acc[i][j] = 0.f;

    const int kbeg = z * 192, kend = kbeg + 192;
    for (int k0 = kbeg; k0 < kend; k0 += 16) {
        float4 va = *(const float4*)(arow + k0 + kg);
        As[kg + 0][row] = va.x; As[kg + 1][row] = va.y;
        As[kg + 2][row] = va.z; As[kg + 3][row] = va.w;
        float4 vb = *(const float4*)(brow + k0 + kg);
        Bs[kg + 0][row] = vb.x; Bs[kg + 1][row] = vb.y;
        Bs[kg + 2][row] = vb.z; Bs[kg + 3][row] = vb.w;
        __syncthreads();

#pragma unroll
        for (int kk = 0; kk < 16; kk++) {
            float a[4], b[4];
            *(float4*)&a[0] = *(const float4*)&As[kk][tm];
            *(float4*)&b[0] = *(const float4*)&Bs[kk][tn];
#pragma unroll
            for (int i = 0; i < 4; i++)
#pragma unroll
                for (int j = 0; j < 4; j++)
                    acc[i][j] = fmaf(a[i], b[j], acc[i][j]);
        }
        __syncthreads();
    }

#pragma unroll
    for (int i = 0; i < 4; i++) {
        float4 o;
        o.x = acc[i][0]; o.y = acc[i][1]; o.z = acc[i][2]; o.w = acc[i][3];
        *(float4*)(&g_WDp[z][(size_t)(m0 + tm + i) * Hdim + n0 + tn]) = o;
    }
}

// ---------------------------------------------------------------------------
// Kernel C: fused scores + masked log-softmax + NLL. One block per (b,t),
// 512 threads, thread per l reading WE^T columns (coalesced).
// ---------------------------------------------------------------------------
__device__ __forceinline__ float selu1(float x) {
    float e = __expf(x);
    return (x > 0.f) ? SELU_SCALE * x : fmaf(SELU_SA, e, -SELU_SA);
}

__global__ __launch_bounds__(512) void score_loss_kernel(
    const float* __restrict__ V,
    const int* __restrict__ xp, const int* __restrict__ yp,
    float* __restrict__ out)
{
    __shared__ float wd_s[Hdim];
    __shared__ float v_s[Hdim];
    __shared__ float red[16];
    __shared__ float bcast;
    __shared__ float gold_s;

    const int bt   = blockIdx.x;
    const int b    = bt >> 4;
    const int tid  = threadIdx.x;
    const int lane = tid & 31;
    const int warp = tid >> 5;

    const int st = idx_stride(xp);
    const int X  = xp[bt * st];
    const int Y  = yp[bt * st];

    for (int i = tid; i < Hdim; i += 512) {
        const size_t o = (size_t)bt * Hdim + i;
        wd_s[i] = (g_WDp[0][o] + g_WDp[1][o]) + (g_WDp[2][o] + g_WDp[3][o]);
        v_s[i]  = V[i];
    }
    __syncthreads();

    const int  l      = X + tid;
    const bool active = (l < Ll);

    float sc = -3.4e38f;
    if (active) {
        const float* col = g_WET + (size_t)b * Ll + l;   // + h*ML per row
        float s0 = 0.f, s1 = 0.f, s2 = 0.f, s3 = 0.f;
#pragma unroll 4
        for (int h = 0; h < Hdim; h += 4) {
            float w0 = col[(size_t)(h + 0) * ML];
            float w1 = col[(size_t)(h + 1) * ML];
            float w2 = col[(size_t)(h + 2) * ML];
            float w3 = col[(size_t)(h + 3) * ML];
            s0 = fmaf(selu1(w0 + wd_s[h + 0]), v_s[h + 0], s0);
            s1 = fmaf(selu1(w1 + wd_s[h + 1]), v_s[h + 1], s1);
            s2 = fmaf(selu1(w2 + wd_s[h + 2]), v_s[h + 2], s2);
            s3 = fmaf(selu1(w3 + wd_s[h + 3]), v_s[h + 3], s3);
        }
        sc = selu1((s0 + s1) + (s2 + s3));
        if (l == Y) gold_s = sc;
    }

    // block max
    float m = sc;
#pragma unroll
    for (int o = 16; o > 0; o >>= 1)
        m = fmaxf(m, __shfl_xor_sync(0xffffffffu, m, o));
    if (lane == 0) red[warp] = m;
    __syncthreads();
    if (tid == 0) {
        float mm = red[0];
#pragma unroll
        for (int i = 1; i < 16; i++) mm = fmaxf(mm, red[i]);
        bcast = mm;
    }
    __syncthreads();
    const float mx = bcast;

    // block sum of exp
    float e = active ? __expf(sc - mx) : 0.f;
#pragma unroll
    for (int o = 16; o > 0; o >>= 1)
        e += __shfl_xor_sync(0xffffffffu, e, o);
    if (lane == 0) red[warp] = e;
    __syncthreads();

    if (tid == 0) {
        float tot = 0.f;
#pragma unroll
        for (int i = 0; i < 16; i++) tot += red[i];
        float lse = mx + __logf(tot);
        atomicAdd(out, (lse - gold_s) * (1.0f / (Bb * Tt)));
    }
}

__global__ void init_out_kernel(float* out) { out[0] = 0.f; }

// ---------------------------------------------------------------------------
extern "C" void kernel_launch(void* const* d_in, const int* in_sizes, int n_in,
                              void* d_out, int out_size) {
    const float* hn  = (const float*)d_in[0];
    const float* dec = (const float*)d_in[1];
    const float* W1  = (const float*)d_in[2];
    const float* W2  = (const float*)d_in[3];
    const float* V   = (const float*)d_in[4];
    const int*   Xi  = (const int*)d_in[5];
    const int*   Yi  = (const int*)d_in[6];
    float* out = (float*)d_out;

    cudaFuncSetAttribute(we_mma_kernel,
                         cudaFuncAttributeMaxDynamicSharedMemorySize, WE_SMEM);

    __nv_bfloat16 *ah, *al, *bh, *bl;
    cudaGetSymbolAddress((void**)&ah, g_Ah);
    cudaGetSymbolAddress((void**)&al, g_Al);
    cudaGetSymbolAddress((void**)&bh, g_Bh);
    cudaGetSymbolAddress((void**)&bl, g_Bl);

    init_out_kernel<<<1, 1>>>(out);

    const int nA4 = (ML * Hdim) / 4;
    const int nW4 = (Hdim * Hdim) / 4;
    split_kernel<<<(nA4 + 255) / 256, 256>>>(hn, ah, al, nA4);
    split_kernel<<<(nW4 + 255) / 256, 256>>>(W1, bh, bl, nW4);

    we_mma_kernel<<<dim3(Hdim / 128, ML / 128), 256, WE_SMEM>>>();
    wd_gemm_kernel<<<dim3(Hdim / 64, (Bb * Tt) / 64, 4), 256>>>(dec, W2, Xi, Yi);
    score_loss_kernel<<<Bb * Tt, 512>>>(V, Xi, Yi, out);
}

// round 17
// speedup vs baseline: 1.3660x; 1.1893x over previous
#include <cuda_runtime.h>
#include <cuda_bf16.h>
#include <cstdint>
#include <math.h>

// Problem constants
#define Bb   16
#define Tt   16
#define Ll   512
#define Hdim 768
#define ML   (Bb * Ll)            // 8192 rows of hn

#define SELU_SCALE 1.0507009873554805f
#define SELU_SA    1.7580993408473766f   // scale * alpha

// Scratch (device globals; no runtime allocation)
__device__ float g_WET[(size_t)Hdim * ML];              // WE^T: [H, B*L]
__device__ float g_WDp[4][(size_t)Bb * Tt * Hdim];      // WD K-split partials
__device__ float g_Sp [4][(size_t)Bb * Tt * Ll];        // score h-chunk partials
__device__ __nv_bfloat16 g_Ah[(size_t)ML * Hdim];       // hn hi
__device__ __nv_bfloat16 g_Al[(size_t)ML * Hdim];       // hn lo
__device__ __nv_bfloat16 g_Bh[(size_t)Hdim * Hdim];     // W1 hi
__device__ __nv_bfloat16 g_Bl[(size_t)Hdim * Hdim];     // W1 lo

__device__ __forceinline__ int idx_stride(const int* __restrict__ xp) {
    return (xp[1] == 0) ? 2 : 1;   // int64 vs int32 index dtype
}

__device__ __forceinline__ uint32_t smem_u32(const void* p) {
    uint32_t a;
    asm("{ .reg .u64 t; cvta.to.shared.u64 t, %1; cvt.u32.u64 %0, t; }"
        : "=r"(a) : "l"(p));
    return a;
}
__device__ __forceinline__ void cp_async16(uint32_t sa, const void* ga) {
    asm volatile("cp.async.cg.shared.global [%0], [%1], 16;"
                 :: "r"(sa), "l"(ga) : "memory");
}
__device__ __forceinline__ void cp_commit() {
    asm volatile("cp.async.commit_group;" ::: "memory");
}
__device__ __forceinline__ void cp_wait0() {
    asm volatile("cp.async.wait_group 0;" ::: "memory");
}
__device__ __forceinline__ void ldsm_x4(uint32_t* r, uint32_t addr) {
    asm volatile("ldmatrix.sync.aligned.m8n8.x4.shared.b16 {%0,%1,%2,%3}, [%4];"
                 : "=r"(r[0]), "=r"(r[1]), "=r"(r[2]), "=r"(r[3]) : "r"(addr));
}
__device__ __forceinline__ void mma_bf16(float* c, const uint32_t* a, const uint32_t* b) {
    asm volatile(
        "mma.sync.aligned.m16n8k16.row.col.f32.bf16.bf16.f32 "
        "{%0,%1,%2,%3}, {%4,%5,%6,%7}, {%8,%9}, {%0,%1,%2,%3};"
        : "+f"(c[0]), "+f"(c[1]), "+f"(c[2]), "+f"(c[3])
        : "r"(a[0]), "r"(a[1]), "r"(a[2]), "r"(a[3]), "r"(b[0]), "r"(b[1]));
}

// ---------------------------------------------------------------------------
// fp32 -> (bf16 hi, bf16 lo) split, vectorized by float4
// ---------------------------------------------------------------------------
__global__ __launch_bounds__(256) void split_kernel(
    const float* __restrict__ src, __nv_bfloat16* __restrict__ hi,
    __nv_bfloat16* __restrict__ lo, int n4)
{
    int i = blockIdx.x * 256 + threadIdx.x;
    if (i >= n4) return;
    float4 v = ((const float4*)src)[i];
    float f[4] = {v.x, v.y, v.z, v.w};
    __nv_bfloat16 h[4], l[4];
#pragma unroll
    for (int j = 0; j < 4; j++) {
        h[j] = __float2bfloat16(f[j]);
        l[j] = __float2bfloat16(f[j] - __bfloat162float(h[j]));
    }
    __nv_bfloat162 h0; h0.x = h[0]; h0.y = h[1];
    __nv_bfloat162 h1; h1.x = h[2]; h1.y = h[3];
    __nv_bfloat162 l0; l0.x = l[0]; l0.y = l[1];
    __nv_bfloat162 l1; l1.x = l[2]; l1.y = l[3];
    ((__nv_bfloat162*)hi)[2 * i]     = h0;
    ((__nv_bfloat162*)hi)[2 * i + 1] = h1;
    ((__nv_bfloat162*)lo)[2 * i]     = l0;
    ((__nv_bfloat162*)lo)[2 * i + 1] = l1;
}

// ---------------------------------------------------------------------------
// Kernel A: WE^T = (hn @ W1^T)^T via mma.sync bf16 split (AhBh + AhBl + AlBh).
// MEASURED 101us: CTA tile 128x128, BK=32, 8 warps each 64x32, cp.async
// 2-stage, 82KB smem -> 2 CTAs/SM co-residency.
// ---------------------------------------------------------------------------
#define ROWB      80
#define TILEB     (128 * ROWB)       // 10240
#define STAGEB    (4 * TILEB)        // 40960
#define WE_SMEM   (2 * STAGEB)       // 81920 >= 128*132*4 epilogue

__global__ __launch_bounds__(256) void we_mma_kernel()
{
    extern __shared__ char smem[];
    const uint32_t sb = smem_u32(smem);

    const int tid    = threadIdx.x;
    const int lane   = tid & 31;
    const int wid    = tid >> 5;
    const int m0     = blockIdx.y * 128;
    const int n0     = blockIdx.x * 128;
    const int warp_m = (wid & 1) * 64;
    const int warp_n = (wid >> 1) * 32;

    const int a_row = lane & 15;
    const int a_ks  = lane >> 4;
    const int b_row = lane & 7;
    const int b_nt  = (lane >> 4);
    const int b_ks  = (lane >> 3) & 1;

    float acc[4][4][4];
#pragma unroll
    for (int i = 0; i < 4; i++)
#pragma unroll
        for (int j = 0; j < 4; j++)
#pragma unroll
            for (int q = 0; q < 4; q++) acc[i][j][q] = 0.f;

    const int r0 = tid >> 2, r1 = (tid + 256) >> 2;
    const int g0 = (tid & 3), g1 = (tid & 3);

    const __nv_bfloat16* srcs[4] = {
        g_Ah + (size_t)m0 * Hdim, g_Al + (size_t)m0 * Hdim,
        g_Bh + (size_t)n0 * Hdim, g_Bl + (size_t)n0 * Hdim };

    auto issue_stage = [&](int s, int c) {
        const uint32_t stb = sb + s * STAGEB;
#pragma unroll
        for (int t = 0; t < 4; t++) {
            const __nv_bfloat16* g = srcs[t] + c * 32;
            cp_async16(stb + t * TILEB + r0 * ROWB + g0 * 16,
                       g + (size_t)r0 * Hdim + g0 * 8);
            cp_async16(stb + t * TILEB + r1 * ROWB + g1 * 16,
                       g + (size_t)r1 * Hdim + g1 * 8);
        }
        cp_commit();
    };

    issue_stage(0, 0);

    for (int c = 0; c < 24; c++) {
        const int s = c & 1;
        cp_wait0();
        __syncthreads();
        if (c + 1 < 24) issue_stage(s ^ 1, c + 1);

        const uint32_t stb = sb + s * STAGEB;
#pragma unroll
        for (int ks = 0; ks < 2; ks++) {
            uint32_t af[4][4], bh[4][2], bl[4][2];
#pragma unroll
            for (int mt = 0; mt < 4; mt++)
                ldsm_x4(af[mt], stb + 0 * TILEB +
                        (warp_m + mt * 16 + a_row) * ROWB + ks * 32 + a_ks * 16);
#pragma unroll
            for (int q = 0; q < 2; q++) {
                uint32_t t4[4];
                ldsm_x4(t4, stb + 2 * TILEB +
                        (warp_n + q * 16 + b_nt * 8 + b_row) * ROWB + ks * 32 + b_ks * 16);
                bh[2 * q][0] = t4[0]; bh[2 * q][1] = t4[1];
                bh[2 * q + 1][0] = t4[2]; bh[2 * q + 1][1] = t4[3];
                ldsm_x4(t4, stb + 3 * TILEB +
                        (warp_n + q * 16 + b_nt * 8 + b_row) * ROWB + ks * 32 + b_ks * 16);
                bl[2 * q][0] = t4[0]; bl[2 * q][1] = t4[1];
                bl[2 * q + 1][0] = t4[2]; bl[2 * q + 1][1] = t4[3];
            }
#pragma unroll
            for (int mt = 0; mt < 4; mt++)
#pragma unroll
                for (int nt = 0; nt < 4; nt++) {
                    mma_bf16(acc[mt][nt], af[mt], bh[nt]);
                    mma_bf16(acc[mt][nt], af[mt], bl[nt]);
                }
#pragma unroll
            for (int mt = 0; mt < 4; mt++)
                ldsm_x4(af[mt], stb + 1 * TILEB +
                        (warp_m + mt * 16 + a_row) * ROWB + ks * 32 + a_ks * 16);
#pragma unroll
            for (int mt = 0; mt < 4; mt++)
#pragma unroll
                for (int nt = 0; nt < 4; nt++)
                    mma_bf16(acc[mt][nt], af[mt], bh[nt]);
        }
    }
    __syncthreads();

    // Epilogue: D -> smem [m][n] (stride 132), then transposed coalesced store
    float (*smT)[132] = (float (*)[132])smem;
    {
        const int rq = lane >> 2;
        const int cq = 2 * (lane & 3);
#pragma unroll
        for (int mt = 0; mt < 4; mt++)
#pragma unroll
            for (int nt = 0; nt < 4; nt++) {
                const int mm = warp_m + mt * 16 + rq;
                const int nn = warp_n + nt * 8 + cq;
                smT[mm][nn]         = acc[mt][nt][0];
                smT[mm][nn + 1]     = acc[mt][nt][1];
                smT[mm + 8][nn]     = acc[mt][nt][2];
                smT[mm + 8][nn + 1] = acc[mt][nt][3];
            }
    }
    __syncthreads();

#pragma unroll
    for (int rr = 0; rr < 16; rr++) {
        const int hh = wid * 16 + rr;
        float4 v;
        v.x = smT[lane * 4 + 0][hh];
        v.y = smT[lane * 4 + 1][hh];
        v.z = smT[lane * 4 + 2][hh];
        v.w = smT[lane * 4 + 3][hh];
        *(float4*)(g_WET + (size_t)(n0 + hh) * ML + m0 + lane * 4) = v;
    }
}

// ---------------------------------------------------------------------------
// Kernel B: WD partials. grid (12, 4, 4); z-block covers K in [z*192, z*192+192).
// ---------------------------------------------------------------------------
__global__ __launch_bounds__(256) void wd_gemm_kernel(
    const float* __restrict__ D, const float* __restrict__ W2,
    const int* __restrict__ xp, const int* __restrict__ yp)
{
    __shared__ float As[16][68];
    __shared__ float Bs[16][68];

    const int st  = idx_stride(xp);
    const int tid = threadIdx.x;
    const int m0  = blockIdx.y * 64;
    const int n0  = blockIdx.x * 64;
    const int z   = blockIdx.z;
    const int tm  = (tid >> 4) * 4;
    const int tn  = (tid & 15) * 4;

    const int row = tid >> 2;
    const int kg  = (tid & 3) * 4;
    const int r   = m0 + row;
    const int bi  = r >> 4;
    const int Yv  = yp[r * st];
    const float* arow = D + ((size_t)bi * Ll + (size_t)Yv) * Hdim;
    const float* brow = W2 + (size_t)(n0 + row) * Hdim;

    float acc[4][4];
#pragma unroll
    for (int i = 0; i < 4; i++)
#pragma unroll
        for (int j = 0; j < 4; j++) acc[i][j] = 0.f;

    const int kbeg = z * 192, kend = kbeg + 192;
    for (int k0 = kbeg; k0 < kend; k0 += 16) {
        float4 va = *(const float4*)(arow + k0 + kg);
        As[kg + 0][row] = va.x; As[kg + 1][row] = va.y;
        As[kg + 2][row] = va.z; As[kg + 3][row] = va.w;
        float4 vb = *(const float4*)(brow + k0 + kg);
        Bs[kg + 0][row] = vb.x; Bs[kg + 1][row] = vb.y;
        Bs[kg + 2][row] = vb.z; Bs[kg + 3][row] = vb.w;
        __syncthreads();

#pragma unroll
        for (int kk = 0; kk < 16; kk++) {
            float a[4], b[4];
            *(float4*)&a[0] = *(const float4*)&As[kk][tm];
            *(float4*)&b[0] = *(const float4*)&Bs[kk][tn];
#pragma unroll
            for (int i = 0; i < 4; i++)
#pragma unroll
                for (int j = 0; j < 4; j++)
                    acc[i][j] = fmaf(a[i], b[j], acc[i][j]);
        }
        __syncthreads();
    }

#pragma unroll
    for (int i = 0; i < 4; i++) {
        float4 o;
        o.x = acc[i][0]; o.y = acc[i][1]; o.z = acc[i][2]; o.w = acc[i][3];
        *(float4*)(&g_WDp[z][(size_t)(m0 + tm + i) * Hdim + n0 + tn]) = o;
    }
}

// ---------------------------------------------------------------------------
// Kernel C1: score partials over h-chunks. grid (256 bt, 4 z); 512 threads,
// thread per l in [X, 512). h in [192z, 192z+192). Partials additive; outer
// selu deferred to the loss kernel.
// ---------------------------------------------------------------------------
__device__ __forceinline__ float selu1(float x) {
    float e = __expf(x);
    return (x > 0.f) ? SELU_SCALE * x : fmaf(SELU_SA, e, -SELU_SA);
}

__global__ __launch_bounds__(512) void score_part_kernel(
    const float* __restrict__ V, const int* __restrict__ xp)
{
    __shared__ float wd_s[192];
    __shared__ float v_s[192];

    const int bt = blockIdx.x;
    const int z  = blockIdx.y;
    const int b  = bt >> 4;
    const int tid = threadIdx.x;
    const int hb  = z * 192;

    const int st = idx_stride(xp);
    const int X  = xp[bt * st];

    if (tid < 192) {
        const size_t o = (size_t)bt * Hdim + hb + tid;
        wd_s[tid] = (g_WDp[0][o] + g_WDp[1][o]) + (g_WDp[2][o] + g_WDp[3][o]);
        v_s[tid]  = V[hb + tid];
    }
    __syncthreads();

    const int l = X + tid;
    if (l >= Ll) return;

    const float* col = g_WET + (size_t)hb * ML + (size_t)b * Ll + l;
    float s0 = 0.f, s1 = 0.f, s2 = 0.f, s3 = 0.f;
#pragma unroll 4
    for (int h = 0; h < 192; h += 4) {
        float w0 = col[(size_t)(h + 0) * ML];
        float w1 = col[(size_t)(h + 1) * ML];
        float w2 = col[(size_t)(h + 2) * ML];
        float w3 = col[(size_t)(h + 3) * ML];
        s0 = fmaf(selu1(w0 + wd_s[h + 0]), v_s[h + 0], s0);
        s1 = fmaf(selu1(w1 + wd_s[h + 1]), v_s[h + 1], s1);
        s2 = fmaf(selu1(w2 + wd_s[h + 2]), v_s[h + 2], s2);
        s3 = fmaf(selu1(w3 + wd_s[h + 3]), v_s[h + 3], s3);
    }
    g_Sp[z][(size_t)bt * Ll + l] = (s0 + s1) + (s2 + s3);
}

// ---------------------------------------------------------------------------
// Kernel C2: combine partials -> selu -> masked log-softmax + NLL.
// ---------------------------------------------------------------------------
__global__ __launch_bounds__(512) void loss_kernel(
    const int* __restrict__ xp, const int* __restrict__ yp,
    float* __restrict__ out)
{
    __shared__ float red[16];
    __shared__ float bcast;
    __shared__ float gold_s;

    const int bt   = blockIdx.x;
    const int tid  = threadIdx.x;
    const int lane = tid & 31;
    const int warp = tid >> 5;

    const int st = idx_stride(xp);
    const int X  = xp[bt * st];
    const int Y  = yp[bt * st];

    const int  l      = X + tid;
    const bool active = (l < Ll);

    float sc = -3.4e38f;
    if (active) {
        const size_t o = (size_t)bt * Ll + l;
        sc = selu1((g_Sp[0][o] + g_Sp[1][o]) + (g_Sp[2][o] + g_Sp[3][o]));
        if (l == Y) gold_s = sc;
    }

    // block max
    float m = sc;
#pragma unroll
    for (int o = 16; o > 0; o >>= 1)
        m = fmaxf(m, __shfl_xor_sync(0xffffffffu, m, o));
    if (lane == 0) red[warp] = m;
    __syncthreads();
    if (tid == 0) {
        float mm = red[0];
#pragma unroll
        for (int i = 1; i < 16; i++) mm = fmaxf(mm, red[i]);
        bcast = mm;
    }
    __syncthreads();
    const float mx = bcast;

    // block sum of exp
    float e = active ? __expf(sc - mx) : 0.f;
#pragma unroll
    for (int o = 16; o > 0; o >>= 1)
        e += __shfl_xor_sync(0xffffffffu, e, o);
    if (lane == 0) red[warp] = e;
    __syncthreads();

    if (tid == 0) {
        float tot = 0.f;
#pragma unroll
        for (int i = 0; i < 16; i++) tot += red[i];
        float lse = mx + __logf(tot);
        atomicAdd(out, (lse - gold_s) * (1.0f / (Bb * Tt)));
    }
}

__global__ void init_out_kernel(float* out) { out[0] = 0.f; }

// ---------------------------------------------------------------------------
extern "C" void kernel_launch(void* const* d_in, const int* in_sizes, int n_in,
                              void* d_out, int out_size) {
    const float* hn  = (const float*)d_in[0];
    const float* dec = (const float*)d_in[1];
    const float* W1  = (const float*)d_in[2];
    const float* W2  = (const float*)d_in[3];
    const float* V   = (const float*)d_in[4];
    const int*   Xi  = (const int*)d_in[5];
    const int*   Yi  = (const int*)d_in[6];
    float* out = (float*)d_out;

    cudaFuncSetAttribute(we_mma_kernel,
                         cudaFuncAttributeMaxDynamicSharedMemorySize, WE_SMEM);

    __nv_bfloat16 *ah, *al, *bh, *bl;
    cudaGetSymbolAddress((void**)&ah, g_Ah);
    cudaGetSymbolAddress((void**)&al, g_Al);
    cudaGetSymbolAddress((void**)&bh, g_Bh);
    cudaGetSymbolAddress((void**)&bl, g_Bl);

    init_out_kernel<<<1, 1>>>(out);

    const int nA4 = (ML * Hdim) / 4;
    const int nW4 = (Hdim * Hdim) / 4;
    split_kernel<<<(nA4 + 255) / 256, 256>>>(hn, ah, al, nA4);
    split_kernel<<<(nW4 + 255) / 256, 256>>>(W1, bh, bl, nW4);

    we_mma_kernel<<<dim3(Hdim / 128, ML / 128), 256, WE_SMEM>>>();
    wd_gemm_kernel<<<dim3(Hdim / 64, (Bb * Tt) / 64, 4), 256>>>(dec, W2, Xi, Yi);
    score_part_kernel<<<dim3(Bb * Tt, 4), 512>>>(V, Xi);
    loss_kernel<<<Bb * Tt, 512>>>(Xi, Yi, out);
}